// round 1
// baseline (speedup 1.0000x reference)
#include <cuda_runtime.h>
#include <cuda_bf16.h>

// ---------------------------------------------------------------------------
// Neural cellular automaton step, fused:
//   perception = conv3x3_wrap(x, w_perc)        [B,48,H,W]
//   h          = relu(w1 @ perception + b1)     [B,96,H,W]
//   update     = (w2 @ h + b2) * (mask > 0.5)
//   out        = x + update
//
// Optimization: fold w1 @ w_perc -> W[108][96] (prep kernel), then stage 1 is
// an implicit-im2col GEMM (M=pixels, N=96, K=108) using packed fma.rn.f32x2.
// B=16, C=12, H=W=384, CP=48, CH=96.
// ---------------------------------------------------------------------------

#define Bn   16
#define Cn   12
#define Hn   384
#define Wn   384
#define CPn  48
#define CHn  96
#define Kn   108          // 12 channels * 9 taps
#define PIX  128          // pixels per block (one row segment)
#define PPAD 130          // smem row width: 128 + 2 halo

typedef unsigned long long u64;

__device__ float g_wcomb[Kn * CHn];   // folded conv weights, [k][o] layout

// ---------------------------------------------------------------------------
// Prep: w_comb[k][o] = sum_p w1[o][p] * w_perc[p][k]   (k = c*9 + dy*3 + dx)
// w1: [96][48] row-major; w_perc: [48][12][3][3] row-major -> [p][k]
// ---------------------------------------------------------------------------
__global__ void fold_kernel(const float* __restrict__ w1,
                            const float* __restrict__ wperc) {
    int k = blockIdx.x;    // 0..107
    int o = threadIdx.x;   // 0..95
    float s = 0.f;
#pragma unroll
    for (int p = 0; p < CPn; ++p)
        s = fmaf(w1[o * CPn + p], wperc[p * Kn + k], s);
    g_wcomb[k * CHn + o] = s;
}

// ---------------------------------------------------------------------------
// Main fused kernel. Grid: (W/128, H, B). Block: 256 threads.
// Thread layout: ty = tid & 15 (hidden group, 6 ch each), tx = tid >> 4
// (pixel group; pixels px = tx + 16*i, i in 0..7). A warp holds 2 tx values
// x 16 ty values, so the hidden-channel reduction in stage 2 is intra-warp.
// ---------------------------------------------------------------------------
__global__ __launch_bounds__(256, 2)
void nca_kernel(const float* __restrict__ x,
                const float* __restrict__ b1,
                const float* __restrict__ w2,
                const float* __restrict__ b2,
                const float* __restrict__ mask,
                float* __restrict__ out) {
    extern __shared__ float sm[];
    float* xs  = sm;                        // 12*3*130 = 4680
    float* ws  = xs + Cn * 3 * PPAD;        // 108*96  = 10368
    float* w2s = ws + Kn * CHn;             // 12*96   = 1152
    float* b1s = w2s + Cn * CHn;            // 96
    float* upd = b1s + CHn;                 // 128*12  = 1536

    const int tid = threadIdx.x;
    const int ty  = tid & 15;
    const int tx  = tid >> 4;
    const int seg = blockIdx.x;
    const int gy  = blockIdx.y;
    const int b   = blockIdx.z;
    const int x0  = seg * PIX;

    // ---- load x patch (with wrap) into smem --------------------------------
    const int ym1 = (gy == 0) ? (Hn - 1) : gy - 1;
    const int yp1 = (gy == Hn - 1) ? 0 : gy + 1;
    int yrow0 = ym1, yrow1 = gy, yrow2 = yp1;
    for (int idx = tid; idx < Cn * 3 * PPAD; idx += 256) {
        int col = idx % PPAD;
        int t   = idx / PPAD;
        int r   = t % 3;
        int c   = t / 3;
        int gyy = (r == 0) ? yrow0 : (r == 1 ? yrow1 : yrow2);
        int gx  = x0 + col - 1;
        gx = (gx < 0) ? gx + Wn : (gx >= Wn ? gx - Wn : gx);
        xs[(c * 3 + r) * PPAD + col] =
            x[((b * Cn + c) * Hn + gyy) * Wn + gx];
    }
    // ---- load weights into smem -------------------------------------------
    for (int idx = tid; idx < Kn * CHn; idx += 256) ws[idx]  = g_wcomb[idx];
    for (int idx = tid; idx < Cn * CHn; idx += 256) w2s[idx] = w2[idx];
    if (tid < CHn) b1s[tid] = b1[tid];
    __syncthreads();

    // ---- stage 1: h[128 px][96 ch] GEMM, K = 108, packed f32x2 FMA --------
    // acc[i][jp] holds hidden channels (ty*6 + 2jp, ty*6 + 2jp + 1) for pixel
    // px = tx + 16*i, as a packed f32x2 in a 64-bit register.
    u64 acc[8][3];
    {
#pragma unroll
        for (int jp = 0; jp < 3; ++jp) {
            float blo = b1s[ty * 6 + 2 * jp];
            float bhi = b1s[ty * 6 + 2 * jp + 1];
            u64 bp;
            asm("mov.b64 %0, {%1, %2};" : "=l"(bp) : "f"(blo), "f"(bhi));
#pragma unroll
            for (int i = 0; i < 8; ++i) acc[i][jp] = bp;
        }
    }

    const float* wrow = ws + ty * 6;
#pragma unroll 1
    for (int c = 0; c < Cn; ++c) {
#pragma unroll
        for (int dy = 0; dy < 3; ++dy) {
            const float* row = &xs[(c * 3 + dy) * PPAD];
#pragma unroll
            for (int dx = 0; dx < 3; ++dx) {
                u64 wv0 = *(const u64*)(wrow + 0);
                u64 wv1 = *(const u64*)(wrow + 2);
                u64 wv2 = *(const u64*)(wrow + 4);
#pragma unroll
                for (int i = 0; i < 8; ++i) {
                    float av = row[dx + tx + 16 * i];
                    u64 ap;
                    asm("mov.b64 %0, {%1, %1};" : "=l"(ap) : "f"(av));
                    asm("fma.rn.f32x2 %0, %1, %2, %0;"
                        : "+l"(acc[i][0]) : "l"(ap), "l"(wv0));
                    asm("fma.rn.f32x2 %0, %1, %2, %0;"
                        : "+l"(acc[i][1]) : "l"(ap), "l"(wv1));
                    asm("fma.rn.f32x2 %0, %1, %2, %0;"
                        : "+l"(acc[i][2]) : "l"(ap), "l"(wv2));
                }
                wrow += CHn;
            }
        }
    }

    // ---- stage 2: update[12] = w2 @ relu(h); reduce over 16 ty lanes ------
    // Process pixels in groups of 4 to bound register pressure.
#pragma unroll 1
    for (int g = 0; g < 2; ++g) {
        float pu[4][12];
#pragma unroll
        for (int i = 0; i < 4; ++i)
#pragma unroll
            for (int oc = 0; oc < 12; ++oc) pu[i][oc] = 0.f;

#pragma unroll
        for (int jp = 0; jp < 3; ++jp) {
#pragma unroll
            for (int half = 0; half < 2; ++half) {
                int j = 2 * jp + half;
                float w2c[12];
#pragma unroll
                for (int oc = 0; oc < 12; ++oc)
                    w2c[oc] = w2s[oc * CHn + ty * 6 + j];
#pragma unroll
                for (int i = 0; i < 4; ++i) {
                    float lo, hi;
                    asm("mov.b64 {%0, %1}, %2;"
                        : "=f"(lo), "=f"(hi) : "l"(acc[g * 4 + i][jp]));
                    float r = fmaxf(half ? hi : lo, 0.f);
#pragma unroll
                    for (int oc = 0; oc < 12; ++oc)
                        pu[i][oc] = fmaf(r, w2c[oc], pu[i][oc]);
                }
            }
        }
        // butterfly reduce over the 16 ty lanes (intra-warp: lane = (tx&1)*16 + ty)
#pragma unroll
        for (int i = 0; i < 4; ++i)
#pragma unroll
            for (int oc = 0; oc < 12; ++oc) {
                float v = pu[i][oc];
                v += __shfl_xor_sync(0xffffffffu, v, 1);
                v += __shfl_xor_sync(0xffffffffu, v, 2);
                v += __shfl_xor_sync(0xffffffffu, v, 4);
                v += __shfl_xor_sync(0xffffffffu, v, 8);
                if (ty == 0)
                    upd[(tx + 16 * (g * 4 + i)) * 12 + oc] = v;
            }
    }

    __syncthreads();

    // ---- epilogue: out = x + (update + b2) * (mask > 0.5) -----------------
    for (int idx = tid; idx < PIX * Cn; idx += 256) {
        int oc = idx >> 7;       // / 128
        int px = idx & 127;
        float m  = (mask[gy * Wn + x0 + px] > 0.5f) ? 1.f : 0.f;
        float xc = xs[(oc * 3 + 1) * PPAD + 1 + px];
        float u  = upd[px * 12 + oc] + __ldg(&b2[oc]);
        out[((b * Cn + oc) * Hn + gy) * Wn + x0 + px] = fmaf(u, m, xc);
    }
}

// ---------------------------------------------------------------------------
extern "C" void kernel_launch(void* const* d_in, const int* in_sizes, int n_in,
                              void* d_out, int out_size) {
    const float* x      = (const float*)d_in[0];
    const float* w_perc = (const float*)d_in[1];
    const float* w1     = (const float*)d_in[2];
    const float* b1     = (const float*)d_in[3];
    const float* w2     = (const float*)d_in[4];
    const float* b2     = (const float*)d_in[5];
    const float* mask   = (const float*)d_in[6];
    float* out          = (float*)d_out;

    const int smem_bytes = (Cn * 3 * PPAD + Kn * CHn + Cn * CHn + CHn +
                            PIX * Cn) * (int)sizeof(float);   // 71328 B
    static int configured = 0;
    // cudaFuncSetAttribute is idempotent and not a stream op; safe every call.
    cudaFuncSetAttribute(nca_kernel,
                         cudaFuncAttributeMaxDynamicSharedMemorySize,
                         smem_bytes);
    (void)configured;

    fold_kernel<<<Kn, CHn>>>(w1, w_perc);
    dim3 grid(Wn / PIX, Hn, Bn);
    nca_kernel<<<grid, 256, smem_bytes>>>(x, b1, w2, b2, mask, out);
}

// round 3
// speedup vs baseline: 1.0008x; 1.0008x over previous
#include <cuda_runtime.h>
#include <cuda_bf16.h>

// ---------------------------------------------------------------------------
// Neural cellular automaton step, fused:
//   perception = conv3x3_wrap(x, w_perc)        [B,48,H,W]
//   h          = relu(w1 @ perception + b1)     [B,96,H,W]
//   update     = (w2 @ h + b2) * (mask > 0.5)
//   out        = x + update
//
// Stage 1 = implicit-im2col GEMM (M=pixels, N=96, K=108) after folding
// w1 @ w_perc -> W[108][96]. Inner loop uses packed fma.rn.f32x2 with a
// DUPLICATED x-patch table in smem so the broadcast f32x2 A-operand comes
// straight from one aligned LDS.64 (no pack MOVs).
// ---------------------------------------------------------------------------

#define Bn   16
#define Cn   12
#define Hn   384
#define Wn   384
#define CPn  48
#define CHn  96
#define Kn   108          // 12 channels * 9 taps
#define PIX  128          // pixels per block (one row segment)
#define PPAD 130          // patch row width: 128 + 2 halo (even -> dup align ok)

typedef unsigned long long u64;

__device__ float g_wcomb[Kn * CHn];   // folded conv weights, [k][o] layout

// ---------------------------------------------------------------------------
// Prep: w_comb[k][o] = sum_p w1[o][p] * w_perc[p][k]   (k = c*9 + dy*3 + dx)
// ---------------------------------------------------------------------------
__global__ void fold_kernel(const float* __restrict__ w1,
                            const float* __restrict__ wperc) {
    int k = blockIdx.x;    // 0..107
    int o = threadIdx.x;   // 0..95
    float s = 0.f;
#pragma unroll
    for (int p = 0; p < CPn; ++p)
        s = fmaf(w1[o * CPn + p], wperc[p * Kn + k], s);
    g_wcomb[k * CHn + o] = s;
}

// ---------------------------------------------------------------------------
// Main fused kernel. Grid: (W/128, H, B). Block: 256 threads.
// ty = tid & 15  -> hidden-channel group (6 ch, as 3 packed f32x2)
// tx = tid >> 4  -> pixel group: 8 CONTIGUOUS pixels px = tx*8 + i.
// A warp = 2 tx values x 16 ty values, so the stage-2 hidden reduction is an
// intra-warp xor-shuffle over lane bits 0..3.
// ---------------------------------------------------------------------------
__global__ __launch_bounds__(256, 2)
void nca_kernel(const float* __restrict__ x,
                const float* __restrict__ b1,
                const float* __restrict__ w2,
                const float* __restrict__ b2,
                const float* __restrict__ mask,
                float* __restrict__ out) {
    extern __shared__ float sm[];
    float* xsd = sm;                        // dup patch: 12*3*130*2 = 9360
    float* ws  = xsd + Cn * 3 * PPAD * 2;   // 108*96  = 10368
    float* w2s = ws + Kn * CHn;             // 12*96   = 1152
    float* b1s = w2s + Cn * CHn;            // 96
    float* upd = b1s + CHn;                 // 128*12  = 1536

    const int tid = threadIdx.x;
    const int ty  = tid & 15;
    const int tx  = tid >> 4;
    const int seg = blockIdx.x;
    const int gy  = blockIdx.y;
    const int b   = blockIdx.z;
    const int x0  = seg * PIX;
    const int pbase = tx * 8;

    // ---- load x patch (wrap) into smem, DUPLICATED as (v,v) pairs ---------
    const int ym1 = (gy == 0) ? (Hn - 1) : gy - 1;
    const int yp1 = (gy == Hn - 1) ? 0 : gy + 1;
    for (int idx = tid; idx < Cn * 3 * PPAD; idx += 256) {
        int col = idx % PPAD;
        int t   = idx / PPAD;
        int r   = t % 3;
        int c   = t / 3;
        int gyy = (r == 0) ? ym1 : (r == 1 ? gy : yp1);
        int gx  = x0 + col - 1;
        gx = (gx < 0) ? gx + Wn : (gx >= Wn ? gx - Wn : gx);
        float v = x[((b * Cn + c) * Hn + gyy) * Wn + gx];
        ((float2*)xsd)[idx] = make_float2(v, v);
    }
    // ---- load weights into smem -------------------------------------------
    for (int idx = tid; idx < Kn * CHn; idx += 256) ws[idx]  = g_wcomb[idx];
    for (int idx = tid; idx < Cn * CHn; idx += 256) w2s[idx] = w2[idx];
    if (tid < CHn) b1s[tid] = b1[tid];
    __syncthreads();

    // ---- stage 1: h[128 px][96 ch] GEMM, K = 108, packed f32x2 FMA --------
    // acc[i][jp]: hidden channels (ty*6+2jp, ty*6+2jp+1) for pixel pbase+i.
    u64 acc[8][3];
    {
#pragma unroll
        for (int jp = 0; jp < 3; ++jp) {
            float blo = b1s[ty * 6 + 2 * jp];
            float bhi = b1s[ty * 6 + 2 * jp + 1];
            u64 bp;
            asm("mov.b64 %0, {%1, %2};" : "=l"(bp) : "f"(blo), "f"(bhi));
#pragma unroll
            for (int i = 0; i < 8; ++i) acc[i][jp] = bp;
        }
    }

    const float* wrow = ws + ty * 6;
#pragma unroll 1
    for (int c = 0; c < Cn; ++c) {
#pragma unroll
        for (int dy = 0; dy < 3; ++dy) {
            const float* rowd = xsd + 2 * ((c * 3 + dy) * PPAD + pbase);
#pragma unroll
            for (int dx = 0; dx < 3; ++dx) {
                u64 wv0 = *(const u64*)(wrow + 0);
                u64 wv1 = *(const u64*)(wrow + 2);
                u64 wv2 = *(const u64*)(wrow + 4);
#pragma unroll
                for (int i = 0; i < 8; ++i) {
                    // duplicated pair (a,a): one aligned 64-bit LDS, no MOVs
                    u64 ap = *(const u64*)(rowd + 2 * (dx + i));
                    asm("fma.rn.f32x2 %0, %1, %2, %0;"
                        : "+l"(acc[i][0]) : "l"(ap), "l"(wv0));
                    asm("fma.rn.f32x2 %0, %1, %2, %0;"
                        : "+l"(acc[i][1]) : "l"(ap), "l"(wv1));
                    asm("fma.rn.f32x2 %0, %1, %2, %0;"
                        : "+l"(acc[i][2]) : "l"(ap), "l"(wv2));
                }
                wrow += CHn;
            }
        }
    }

    // ---- stage 2: update[12] = w2 @ relu(h); reduce over 16 ty lanes ------
#pragma unroll 1
    for (int g = 0; g < 2; ++g) {
        float pu[4][12];
#pragma unroll
        for (int i = 0; i < 4; ++i)
#pragma unroll
            for (int oc = 0; oc < 12; ++oc) pu[i][oc] = 0.f;

#pragma unroll
        for (int jp = 0; jp < 3; ++jp) {
#pragma unroll
            for (int half = 0; half < 2; ++half) {
                int j = 2 * jp + half;
                float w2c[12];
#pragma unroll
                for (int oc = 0; oc < 12; ++oc)
                    w2c[oc] = w2s[oc * CHn + ty * 6 + j];
#pragma unroll
                for (int i = 0; i < 4; ++i) {
                    float lo, hi;
                    asm("mov.b64 {%0, %1}, %2;"
                        : "=f"(lo), "=f"(hi) : "l"(acc[g * 4 + i][jp]));
                    float r = fmaxf(half ? hi : lo, 0.f);
#pragma unroll
                    for (int oc = 0; oc < 12; ++oc)
                        pu[i][oc] = fmaf(r, w2c[oc], pu[i][oc]);
                }
            }
        }
        // butterfly reduce over the 16 ty lanes (lane bits 0..3)
#pragma unroll
        for (int i = 0; i < 4; ++i)
#pragma unroll
            for (int oc = 0; oc < 12; ++oc) {
                float v = pu[i][oc];
                v += __shfl_xor_sync(0xffffffffu, v, 1);
                v += __shfl_xor_sync(0xffffffffu, v, 2);
                v += __shfl_xor_sync(0xffffffffu, v, 4);
                v += __shfl_xor_sync(0xffffffffu, v, 8);
                if (ty == 0)
                    upd[(pbase + g * 4 + i) * 12 + oc] = v;
            }
    }

    __syncthreads();

    // ---- epilogue: out = x + (update + b2) * (mask > 0.5) -----------------
    for (int idx = tid; idx < PIX * Cn; idx += 256) {
        int oc = idx >> 7;       // / 128
        int px = idx & 127;
        float m  = (mask[gy * Wn + x0 + px] > 0.5f) ? 1.f : 0.f;
        float xc = xsd[2 * ((oc * 3 + 1) * PPAD + 1 + px)];   // lo of dup pair
        float u  = upd[px * 12 + oc] + __ldg(&b2[oc]);
        out[((b * Cn + oc) * Hn + gy) * Wn + x0 + px] = fmaf(u, m, xc);
    }
}

// ---------------------------------------------------------------------------
extern "C" void kernel_launch(void* const* d_in, const int* in_sizes, int n_in,
                              void* d_out, int out_size) {
    const float* x      = (const float*)d_in[0];
    const float* w_perc = (const float*)d_in[1];
    const float* w1     = (const float*)d_in[2];
    const float* b1     = (const float*)d_in[3];
    const float* w2     = (const float*)d_in[4];
    const float* b2     = (const float*)d_in[5];
    const float* mask   = (const float*)d_in[6];
    float* out          = (float*)d_out;

    const int smem_bytes = (Cn * 3 * PPAD * 2 + Kn * CHn + Cn * CHn + CHn +
                            PIX * Cn) * (int)sizeof(float);   // 90048 B
    cudaFuncSetAttribute(nca_kernel,
                         cudaFuncAttributeMaxDynamicSharedMemorySize,
                         smem_bytes);

    fold_kernel<<<Kn, CHn>>>(w1, w_perc);
    dim3 grid(Wn / PIX, Hn, Bn);
    nca_kernel<<<grid, 256, smem_bytes>>>(x, b1, w2, b2, mask, out);
}

// round 4
// speedup vs baseline: 1.0916x; 1.0907x over previous
#include <cuda_runtime.h>
#include <cuda_bf16.h>

// ---------------------------------------------------------------------------
// Neural cellular automaton step, fused:
//   perception = conv3x3_wrap(x, w_perc)        [B,48,H,W]
//   h          = relu(w1 @ perception + b1)     [B,96,H,W]
//   update     = (w2 @ h + b2) * (mask > 0.5)
//   out        = x + update
//
// Stage 1 = implicit-im2col GEMM (M=pixels, N=96, K=108) after folding
// w1 @ w_perc -> W[108][96]. Packed fma.rn.f32x2 with a register-cached
// sliding A-window (10 dup-pairs per (c,dy) row via 5 LDS.128) to push the
// LDS:FFMA2 ratio from 1.38 down to 0.19 -> FMA-pipe-bound.
// ---------------------------------------------------------------------------

#define Bn   16
#define Cn   12
#define Hn   384
#define Wn   384
#define CPn  48
#define CHn  96
#define Kn   108          // 12 channels * 9 taps
#define PIX  128          // pixels per block (one row segment)
#define PPAD 130          // patch row width: 128 + 2 halo (even -> align ok)

typedef unsigned long long u64;

__device__ float g_wcomb[Kn * CHn];   // folded conv weights, [k][o] layout

// ---------------------------------------------------------------------------
// Prep: w_comb[k][o] = sum_p w1[o][p] * w_perc[p][k]   (k = c*9 + dy*3 + dx)
// ---------------------------------------------------------------------------
__global__ void fold_kernel(const float* __restrict__ w1,
                            const float* __restrict__ wperc) {
    int k = blockIdx.x;    // 0..107
    int o = threadIdx.x;   // 0..95
    float s = 0.f;
#pragma unroll
    for (int p = 0; p < CPn; ++p)
        s = fmaf(w1[o * CPn + p], wperc[p * Kn + k], s);
    g_wcomb[k * CHn + o] = s;
}

// ---------------------------------------------------------------------------
// Main fused kernel. Grid: (W/128, H, B). Block: 256 threads.
// ty = tid & 15  -> hidden-channel group (6 ch, as 3 packed f32x2)
// tx = tid >> 4  -> pixel group: 8 CONTIGUOUS pixels px = tx*8 + i.
// A warp = 2 tx values x 16 ty values, so the stage-2 hidden reduction is an
// intra-warp xor-shuffle over lane bits 0..3.
// ---------------------------------------------------------------------------
__global__ __launch_bounds__(256, 2)
void nca_kernel(const float* __restrict__ x,
                const float* __restrict__ b1,
                const float* __restrict__ w2,
                const float* __restrict__ b2,
                const float* __restrict__ mask,
                float* __restrict__ out) {
    extern __shared__ float sm[];
    float* xsd = sm;                        // dup patch: 12*3*130*2 = 9360
    float* ws  = xsd + Cn * 3 * PPAD * 2;   // 108*96  = 10368
    float* w2s = ws + Kn * CHn;             // 12*96   = 1152
    float* b1s = w2s + Cn * CHn;            // 96
    float* upd = b1s + CHn;                 // 128*12  = 1536

    const int tid = threadIdx.x;
    const int ty  = tid & 15;
    const int tx  = tid >> 4;
    const int seg = blockIdx.x;
    const int gy  = blockIdx.y;
    const int b   = blockIdx.z;
    const int x0  = seg * PIX;
    const int pbase = tx * 8;

    // ---- load x patch (wrap) into smem, DUPLICATED as (v,v) pairs ---------
    const int ym1 = (gy == 0) ? (Hn - 1) : gy - 1;
    const int yp1 = (gy == Hn - 1) ? 0 : gy + 1;
    for (int idx = tid; idx < Cn * 3 * PPAD; idx += 256) {
        int col = idx % PPAD;
        int t   = idx / PPAD;
        int r   = t % 3;
        int c   = t / 3;
        int gyy = (r == 0) ? ym1 : (r == 1 ? gy : yp1);
        int gx  = x0 + col - 1;
        gx = (gx < 0) ? gx + Wn : (gx >= Wn ? gx - Wn : gx);
        float v = x[((b * Cn + c) * Hn + gyy) * Wn + gx];
        ((float2*)xsd)[idx] = make_float2(v, v);
    }
    // ---- load weights into smem -------------------------------------------
    for (int idx = tid; idx < Kn * CHn; idx += 256) ws[idx]  = g_wcomb[idx];
    for (int idx = tid; idx < Cn * CHn; idx += 256) w2s[idx] = w2[idx];
    if (tid < CHn) b1s[tid] = b1[tid];
    __syncthreads();

    // ---- stage 1: h[128 px][96 ch] GEMM, K = 108, packed f32x2 FMA --------
    // acc[i][jp]: hidden channels (ty*6+2jp, ty*6+2jp+1) for pixel pbase+i.
    u64 acc[8][3];
    {
#pragma unroll
        for (int jp = 0; jp < 3; ++jp) {
            float blo = b1s[ty * 6 + 2 * jp];
            float bhi = b1s[ty * 6 + 2 * jp + 1];
            u64 bp;
            asm("mov.b64 %0, {%1, %2};" : "=l"(bp) : "f"(blo), "f"(bhi));
#pragma unroll
            for (int i = 0; i < 8; ++i) acc[i][jp] = bp;
        }
    }

    // dup-pair view of the patch: one u64 per logical patch element
    const u64* winp = (const u64*)xsd + pbase;   // advances PPAD per row
    const float* wrow = ws + ty * 6;             // advances CHn per k

#pragma unroll 1
    for (int row = 0; row < Cn * 3; ++row) {
        // register-cached sliding window: 10 dup-pairs via 5 LDS.128
        u64 win[10];
#pragma unroll
        for (int p = 0; p < 10; p += 2) {
            ulonglong2 v = *(const ulonglong2*)(winp + p);
            win[p]     = v.x;
            win[p + 1] = v.y;
        }
#pragma unroll
        for (int dx = 0; dx < 3; ++dx) {
            u64 wv0 = *(const u64*)(wrow + 0);
            u64 wv1 = *(const u64*)(wrow + 2);
            u64 wv2 = *(const u64*)(wrow + 4);
#pragma unroll
            for (int i = 0; i < 8; ++i) {
                u64 ap = win[dx + i];
                asm("fma.rn.f32x2 %0, %1, %2, %0;"
                    : "+l"(acc[i][0]) : "l"(ap), "l"(wv0));
                asm("fma.rn.f32x2 %0, %1, %2, %0;"
                    : "+l"(acc[i][1]) : "l"(ap), "l"(wv1));
                asm("fma.rn.f32x2 %0, %1, %2, %0;"
                    : "+l"(acc[i][2]) : "l"(ap), "l"(wv2));
            }
            wrow += CHn;
        }
        winp += PPAD;
    }

    // ---- stage 2: update[12] = w2 @ relu(h); reduce over 16 ty lanes ------
#pragma unroll 1
    for (int g = 0; g < 2; ++g) {
        float pu[4][12];
#pragma unroll
        for (int i = 0; i < 4; ++i)
#pragma unroll
            for (int oc = 0; oc < 12; ++oc) pu[i][oc] = 0.f;

#pragma unroll
        for (int jp = 0; jp < 3; ++jp) {
#pragma unroll
            for (int half = 0; half < 2; ++half) {
                int j = 2 * jp + half;
                float w2c[12];
#pragma unroll
                for (int oc = 0; oc < 12; ++oc)
                    w2c[oc] = w2s[oc * CHn + ty * 6 + j];
#pragma unroll
                for (int i = 0; i < 4; ++i) {
                    float lo, hi;
                    asm("mov.b64 {%0, %1}, %2;"
                        : "=f"(lo), "=f"(hi) : "l"(acc[g * 4 + i][jp]));
                    float r = fmaxf(half ? hi : lo, 0.f);
#pragma unroll
                    for (int oc = 0; oc < 12; ++oc)
                        pu[i][oc] = fmaf(r, w2c[oc], pu[i][oc]);
                }
            }
        }
        // butterfly reduce over the 16 ty lanes (lane bits 0..3)
#pragma unroll
        for (int i = 0; i < 4; ++i)
#pragma unroll
            for (int oc = 0; oc < 12; ++oc) {
                float v = pu[i][oc];
                v += __shfl_xor_sync(0xffffffffu, v, 1);
                v += __shfl_xor_sync(0xffffffffu, v, 2);
                v += __shfl_xor_sync(0xffffffffu, v, 4);
                v += __shfl_xor_sync(0xffffffffu, v, 8);
                if (ty == 0)
                    upd[(pbase + g * 4 + i) * 12 + oc] = v;
            }
    }

    __syncthreads();

    // ---- epilogue: out = x + (update + b2) * (mask > 0.5) -----------------
    for (int idx = tid; idx < PIX * Cn; idx += 256) {
        int oc = idx >> 7;       // / 128
        int px = idx & 127;
        float m  = (mask[gy * Wn + x0 + px] > 0.5f) ? 1.f : 0.f;
        float xc = xsd[2 * ((oc * 3 + 1) * PPAD + 1 + px)];   // lo of dup pair
        float u  = upd[px * 12 + oc] + __ldg(&b2[oc]);
        out[((b * Cn + oc) * Hn + gy) * Wn + x0 + px] = fmaf(u, m, xc);
    }
}

// ---------------------------------------------------------------------------
extern "C" void kernel_launch(void* const* d_in, const int* in_sizes, int n_in,
                              void* d_out, int out_size) {
    const float* x      = (const float*)d_in[0];
    const float* w_perc = (const float*)d_in[1];
    const float* w1     = (const float*)d_in[2];
    const float* b1     = (const float*)d_in[3];
    const float* w2     = (const float*)d_in[4];
    const float* b2     = (const float*)d_in[5];
    const float* mask   = (const float*)d_in[6];
    float* out          = (float*)d_out;

    const int smem_bytes = (Cn * 3 * PPAD * 2 + Kn * CHn + Cn * CHn + CHn +
                            PIX * Cn) * (int)sizeof(float);   // 90048 B
    cudaFuncSetAttribute(nca_kernel,
                         cudaFuncAttributeMaxDynamicSharedMemorySize,
                         smem_bytes);

    fold_kernel<<<Kn, CHn>>>(w1, w_perc);
    dim3 grid(Wn / PIX, Hn, Bn);
    nca_kernel<<<grid, 256, smem_bytes>>>(x, b1, w2, b2, mask, out);
}

// round 5
// speedup vs baseline: 1.1160x; 1.0224x over previous
#include <cuda_runtime.h>
#include <cuda_bf16.h>

// ---------------------------------------------------------------------------
// Neural cellular automaton step, fused:
//   perception = conv3x3_wrap(x, w_perc)        [B,48,H,W]
//   h          = relu(w1 @ perception + b1)     [B,96,H,W]
//   update     = (w2 @ h + b2) * (mask > 0.5)
//   out        = x + update
//
// Stage 1 = implicit-im2col GEMM (M=pixels, N=96, K=108) after folding
// w1 @ w_perc -> W[108][96]. Packed fma.rn.f32x2. All loads for a k-row
// (A window dup-pairs + all 9 W pairs) are batched at the row top so their
// latencies pipeline (MLP=14), then a pure 72-FFMA2 burst follows.
// ---------------------------------------------------------------------------

#define Bn   16
#define Cn   12
#define Hn   384
#define Wn   384
#define CPn  48
#define CHn  96
#define Kn   108          // 12 channels * 9 taps
#define PIX  128          // pixels per block (one row segment)
#define PPAD 130          // patch row width: 128 + 2 halo (even -> align ok)

typedef unsigned long long u64;

__device__ float g_wcomb[Kn * CHn];   // folded conv weights, [k][o] layout

// ---------------------------------------------------------------------------
// Prep: w_comb[k][o] = sum_p w1[o][p] * w_perc[p][k]   (k = c*9 + dy*3 + dx)
// ---------------------------------------------------------------------------
__global__ void fold_kernel(const float* __restrict__ w1,
                            const float* __restrict__ wperc) {
    int k = blockIdx.x;    // 0..107
    int o = threadIdx.x;   // 0..95
    float s = 0.f;
#pragma unroll
    for (int p = 0; p < CPn; ++p)
        s = fmaf(w1[o * CPn + p], wperc[p * Kn + k], s);
    g_wcomb[k * CHn + o] = s;
}

// ---------------------------------------------------------------------------
// Main fused kernel. Grid: (W/128, H, B). Block: 256 threads.
// ty = tid & 15  -> hidden-channel group (6 ch, as 3 packed f32x2)
// tx = tid >> 4  -> pixel group: 8 CONTIGUOUS pixels px = tx*8 + i.
// A warp = 2 tx values x 16 ty values, so the stage-2 hidden reduction is an
// intra-warp xor-shuffle over lane bits 0..3.
// ---------------------------------------------------------------------------
__global__ __launch_bounds__(256, 2)
void nca_kernel(const float* __restrict__ x,
                const float* __restrict__ b1,
                const float* __restrict__ w2,
                const float* __restrict__ b2,
                const float* __restrict__ mask,
                float* __restrict__ out) {
    extern __shared__ float sm[];
    float* xsd = sm;                        // dup patch: 12*3*130*2 = 9360
    float* ws  = xsd + Cn * 3 * PPAD * 2;   // 108*96  = 10368
    float* w2s = ws + Kn * CHn;             // 12*96   = 1152
    float* b1s = w2s + Cn * CHn;            // 96
    float* upd = b1s + CHn;                 // 128*12  = 1536

    const int tid = threadIdx.x;
    const int ty  = tid & 15;
    const int tx  = tid >> 4;
    const int seg = blockIdx.x;
    const int gy  = blockIdx.y;
    const int b   = blockIdx.z;
    const int x0  = seg * PIX;
    const int pbase = tx * 8;

    // ---- load x patch (wrap) into smem, DUPLICATED as (v,v) pairs ---------
    const int ym1 = (gy == 0) ? (Hn - 1) : gy - 1;
    const int yp1 = (gy == Hn - 1) ? 0 : gy + 1;
    for (int idx = tid; idx < Cn * 3 * PPAD; idx += 256) {
        int col = idx % PPAD;
        int t   = idx / PPAD;
        int r   = t % 3;
        int c   = t / 3;
        int gyy = (r == 0) ? ym1 : (r == 1 ? gy : yp1);
        int gx  = x0 + col - 1;
        gx = (gx < 0) ? gx + Wn : (gx >= Wn ? gx - Wn : gx);
        float v = x[((b * Cn + c) * Hn + gyy) * Wn + gx];
        ((float2*)xsd)[idx] = make_float2(v, v);
    }
    // ---- load weights into smem -------------------------------------------
    for (int idx = tid; idx < Kn * CHn; idx += 256) ws[idx]  = g_wcomb[idx];
    for (int idx = tid; idx < Cn * CHn; idx += 256) w2s[idx] = w2[idx];
    if (tid < CHn) b1s[tid] = b1[tid];
    __syncthreads();

    // ---- stage 1: h[128 px][96 ch] GEMM, K = 108, packed f32x2 FMA --------
    // acc[i][jp]: hidden channels (ty*6+2jp, ty*6+2jp+1) for pixel pbase+i.
    u64 acc[8][3];
    {
#pragma unroll
        for (int jp = 0; jp < 3; ++jp) {
            float blo = b1s[ty * 6 + 2 * jp];
            float bhi = b1s[ty * 6 + 2 * jp + 1];
            u64 bp;
            asm("mov.b64 %0, {%1, %2};" : "=l"(bp) : "f"(blo), "f"(bhi));
#pragma unroll
            for (int i = 0; i < 8; ++i) acc[i][jp] = bp;
        }
    }

    // dup-pair view of the patch: one u64 per logical patch element
    const u64* winp = (const u64*)xsd + pbase;   // advances PPAD per row
    const float* wrow = ws + ty * 6;             // advances 3*CHn per row

#pragma unroll 1
    for (int row = 0; row < Cn * 3; ++row) {
        // ---- batched row loads: 5 LDS.128 (A window) + 9 LDS.64 (W) ------
        u64 win[10];
#pragma unroll
        for (int p = 0; p < 10; p += 2) {
            ulonglong2 v = *(const ulonglong2*)(winp + p);
            win[p]     = v.x;
            win[p + 1] = v.y;
        }
        u64 wv[9];
#pragma unroll
        for (int dx = 0; dx < 3; ++dx) {
            wv[dx * 3 + 0] = *(const u64*)(wrow + dx * CHn + 0);
            wv[dx * 3 + 1] = *(const u64*)(wrow + dx * CHn + 2);
            wv[dx * 3 + 2] = *(const u64*)(wrow + dx * CHn + 4);
        }
        // ---- pure FMA burst: 72 FFMA2, no interior loads -----------------
#pragma unroll
        for (int dx = 0; dx < 3; ++dx) {
#pragma unroll
            for (int i = 0; i < 8; ++i) {
                u64 ap = win[dx + i];
                asm("fma.rn.f32x2 %0, %1, %2, %0;"
                    : "+l"(acc[i][0]) : "l"(ap), "l"(wv[dx * 3 + 0]));
                asm("fma.rn.f32x2 %0, %1, %2, %0;"
                    : "+l"(acc[i][1]) : "l"(ap), "l"(wv[dx * 3 + 1]));
                asm("fma.rn.f32x2 %0, %1, %2, %0;"
                    : "+l"(acc[i][2]) : "l"(ap), "l"(wv[dx * 3 + 2]));
            }
        }
        wrow += 3 * CHn;
        winp += PPAD;
    }

    // ---- stage 2: update[12] = w2 @ relu(h); reduce over 16 ty lanes ------
    // Pixel groups of 2 to keep register pressure low (pu = 24 regs).
#pragma unroll 1
    for (int g = 0; g < 4; ++g) {
        float pu[2][12];
#pragma unroll
        for (int i = 0; i < 2; ++i)
#pragma unroll
            for (int oc = 0; oc < 12; ++oc) pu[i][oc] = 0.f;

#pragma unroll
        for (int jp = 0; jp < 3; ++jp) {
#pragma unroll
            for (int half = 0; half < 2; ++half) {
                int j = 2 * jp + half;
                float w2c[12];
#pragma unroll
                for (int oc = 0; oc < 12; ++oc)
                    w2c[oc] = w2s[oc * CHn + ty * 6 + j];
#pragma unroll
                for (int i = 0; i < 2; ++i) {
                    float lo, hi;
                    asm("mov.b64 {%0, %1}, %2;"
                        : "=f"(lo), "=f"(hi) : "l"(acc[g * 2 + i][jp]));
                    float r = fmaxf(half ? hi : lo, 0.f);
#pragma unroll
                    for (int oc = 0; oc < 12; ++oc)
                        pu[i][oc] = fmaf(r, w2c[oc], pu[i][oc]);
                }
            }
        }
        // butterfly reduce over the 16 ty lanes (lane bits 0..3)
#pragma unroll
        for (int i = 0; i < 2; ++i)
#pragma unroll
            for (int oc = 0; oc < 12; ++oc) {
                float v = pu[i][oc];
                v += __shfl_xor_sync(0xffffffffu, v, 1);
                v += __shfl_xor_sync(0xffffffffu, v, 2);
                v += __shfl_xor_sync(0xffffffffu, v, 4);
                v += __shfl_xor_sync(0xffffffffu, v, 8);
                if (ty == 0)
                    upd[(pbase + g * 2 + i) * 12 + oc] = v;
            }
    }

    __syncthreads();

    // ---- epilogue: out = x + (update + b2) * (mask > 0.5) -----------------
    for (int idx = tid; idx < PIX * Cn; idx += 256) {
        int oc = idx >> 7;       // / 128
        int px = idx & 127;
        float m  = (mask[gy * Wn + x0 + px] > 0.5f) ? 1.f : 0.f;
        float xc = xsd[2 * ((oc * 3 + 1) * PPAD + 1 + px)];   // lo of dup pair
        float u  = upd[px * 12 + oc] + __ldg(&b2[oc]);
        out[((b * Cn + oc) * Hn + gy) * Wn + x0 + px] = fmaf(u, m, xc);
    }
}

// ---------------------------------------------------------------------------
extern "C" void kernel_launch(void* const* d_in, const int* in_sizes, int n_in,
                              void* d_out, int out_size) {
    const float* x      = (const float*)d_in[0];
    const float* w_perc = (const float*)d_in[1];
    const float* w1     = (const float*)d_in[2];
    const float* b1     = (const float*)d_in[3];
    const float* w2     = (const float*)d_in[4];
    const float* b2     = (const float*)d_in[5];
    const float* mask   = (const float*)d_in[6];
    float* out          = (float*)d_out;

    const int smem_bytes = (Cn * 3 * PPAD * 2 + Kn * CHn + Cn * CHn + CHn +
                            PIX * Cn) * (int)sizeof(float);   // 90048 B
    cudaFuncSetAttribute(nca_kernel,
                         cudaFuncAttributeMaxDynamicSharedMemorySize,
                         smem_bytes);

    fold_kernel<<<Kn, CHn>>>(w1, w_perc);
    dim3 grid(Wn / PIX, Hn, Bn);
    nca_kernel<<<grid, 256, smem_bytes>>>(x, b1, w2, b2, mask, out);
}

// round 6
// speedup vs baseline: 1.1164x; 1.0003x over previous
#include <cuda_runtime.h>
#include <cuda_bf16.h>

// ---------------------------------------------------------------------------
// Neural cellular automaton step, fused:
//   perception = conv3x3_wrap(x, w_perc)        [B,48,H,W]
//   h          = relu(w1 @ perception + b1)     [B,96,H,W]
//   update     = (w2 @ h + b2) * (mask > 0.5)
//   out        = x + update
//
// Stage 1 = implicit-im2col GEMM (M=pixels, N=96, K=108) after folding
// w1 @ w_perc -> W[108][96]. Packed fma.rn.f32x2. All loads for a k-row
// (A window dup-pairs + all 9 W pairs) are batched at the row top so their
// latencies pipeline (MLP=14), then a pure 72-FFMA2 burst follows.
// ---------------------------------------------------------------------------

#define Bn   16
#define Cn   12
#define Hn   384
#define Wn   384
#define CPn  48
#define CHn  96
#define Kn   108          // 12 channels * 9 taps
#define PIX  128          // pixels per block (one row segment)
#define PPAD 130          // patch row width: 128 + 2 halo (even -> align ok)

typedef unsigned long long u64;

__device__ float g_wcomb[Kn * CHn];   // folded conv weights, [k][o] layout

// ---------------------------------------------------------------------------
// Prep: w_comb[k][o] = sum_p w1[o][p] * w_perc[p][k]   (k = c*9 + dy*3 + dx)
// ---------------------------------------------------------------------------
__global__ void fold_kernel(const float* __restrict__ w1,
                            const float* __restrict__ wperc) {
    int k = blockIdx.x;    // 0..107
    int o = threadIdx.x;   // 0..95
    float s = 0.f;
#pragma unroll
    for (int p = 0; p < CPn; ++p)
        s = fmaf(w1[o * CPn + p], wperc[p * Kn + k], s);
    g_wcomb[k * CHn + o] = s;
}

// ---------------------------------------------------------------------------
// Main fused kernel. Grid: (W/128, H, B). Block: 256 threads.
// ty = tid & 15  -> hidden-channel group (6 ch, as 3 packed f32x2)
// tx = tid >> 4  -> pixel group: 8 CONTIGUOUS pixels px = tx*8 + i.
// A warp = 2 tx values x 16 ty values, so the stage-2 hidden reduction is an
// intra-warp xor-shuffle over lane bits 0..3.
// ---------------------------------------------------------------------------
__global__ __launch_bounds__(256, 2)
void nca_kernel(const float* __restrict__ x,
                const float* __restrict__ b1,
                const float* __restrict__ w2,
                const float* __restrict__ b2,
                const float* __restrict__ mask,
                float* __restrict__ out) {
    extern __shared__ float sm[];
    float* xsd = sm;                        // dup patch: 12*3*130*2 = 9360
    float* ws  = xsd + Cn * 3 * PPAD * 2;   // 108*96  = 10368
    float* w2s = ws + Kn * CHn;             // 12*96   = 1152
    float* b1s = w2s + Cn * CHn;            // 96
    float* upd = b1s + CHn;                 // 128*12  = 1536

    const int tid = threadIdx.x;
    const int ty  = tid & 15;
    const int tx  = tid >> 4;
    const int seg = blockIdx.x;
    const int gy  = blockIdx.y;
    const int b   = blockIdx.z;
    const int x0  = seg * PIX;
    const int pbase = tx * 8;

    // ---- load x patch (wrap) into smem, DUPLICATED as (v,v) pairs ---------
    const int ym1 = (gy == 0) ? (Hn - 1) : gy - 1;
    const int yp1 = (gy == Hn - 1) ? 0 : gy + 1;
    for (int idx = tid; idx < Cn * 3 * PPAD; idx += 256) {
        int col = idx % PPAD;
        int t   = idx / PPAD;
        int r   = t % 3;
        int c   = t / 3;
        int gyy = (r == 0) ? ym1 : (r == 1 ? gy : yp1);
        int gx  = x0 + col - 1;
        gx = (gx < 0) ? gx + Wn : (gx >= Wn ? gx - Wn : gx);
        float v = x[((b * Cn + c) * Hn + gyy) * Wn + gx];
        ((float2*)xsd)[idx] = make_float2(v, v);
    }
    // ---- load weights into smem -------------------------------------------
    for (int idx = tid; idx < Kn * CHn; idx += 256) ws[idx]  = g_wcomb[idx];
    for (int idx = tid; idx < Cn * CHn; idx += 256) w2s[idx] = w2[idx];
    if (tid < CHn) b1s[tid] = b1[tid];
    __syncthreads();

    // ---- stage 1: h[128 px][96 ch] GEMM, K = 108, packed f32x2 FMA --------
    // acc[i][jp]: hidden channels (ty*6+2jp, ty*6+2jp+1) for pixel pbase+i.
    u64 acc[8][3];
    {
#pragma unroll
        for (int jp = 0; jp < 3; ++jp) {
            float blo = b1s[ty * 6 + 2 * jp];
            float bhi = b1s[ty * 6 + 2 * jp + 1];
            u64 bp;
            asm("mov.b64 %0, {%1, %2};" : "=l"(bp) : "f"(blo), "f"(bhi));
#pragma unroll
            for (int i = 0; i < 8; ++i) acc[i][jp] = bp;
        }
    }

    // dup-pair view of the patch: one u64 per logical patch element
    const u64* winp = (const u64*)xsd + pbase;   // advances PPAD per row
    const float* wrow = ws + ty * 6;             // advances 3*CHn per row

#pragma unroll 1
    for (int row = 0; row < Cn * 3; ++row) {
        // ---- batched row loads: 5 LDS.128 (A window) + 9 LDS.64 (W) ------
        u64 win[10];
#pragma unroll
        for (int p = 0; p < 10; p += 2) {
            ulonglong2 v = *(const ulonglong2*)(winp + p);
            win[p]     = v.x;
            win[p + 1] = v.y;
        }
        u64 wv[9];
#pragma unroll
        for (int dx = 0; dx < 3; ++dx) {
            wv[dx * 3 + 0] = *(const u64*)(wrow + dx * CHn + 0);
            wv[dx * 3 + 1] = *(const u64*)(wrow + dx * CHn + 2);
            wv[dx * 3 + 2] = *(const u64*)(wrow + dx * CHn + 4);
        }
        // ---- pure FMA burst: 72 FFMA2, no interior loads -----------------
#pragma unroll
        for (int dx = 0; dx < 3; ++dx) {
#pragma unroll
            for (int i = 0; i < 8; ++i) {
                u64 ap = win[dx + i];
                asm("fma.rn.f32x2 %0, %1, %2, %0;"
                    : "+l"(acc[i][0]) : "l"(ap), "l"(wv[dx * 3 + 0]));
                asm("fma.rn.f32x2 %0, %1, %2, %0;"
                    : "+l"(acc[i][1]) : "l"(ap), "l"(wv[dx * 3 + 1]));
                asm("fma.rn.f32x2 %0, %1, %2, %0;"
                    : "+l"(acc[i][2]) : "l"(ap), "l"(wv[dx * 3 + 2]));
            }
        }
        wrow += 3 * CHn;
        winp += PPAD;
    }

    // ---- stage 2: update[12] = w2 @ relu(h); reduce over 16 ty lanes ------
    // Pixel groups of 2 to keep register pressure low (pu = 24 regs).
#pragma unroll 1
    for (int g = 0; g < 4; ++g) {
        float pu[2][12];
#pragma unroll
        for (int i = 0; i < 2; ++i)
#pragma unroll
            for (int oc = 0; oc < 12; ++oc) pu[i][oc] = 0.f;

#pragma unroll
        for (int jp = 0; jp < 3; ++jp) {
#pragma unroll
            for (int half = 0; half < 2; ++half) {
                int j = 2 * jp + half;
                float w2c[12];
#pragma unroll
                for (int oc = 0; oc < 12; ++oc)
                    w2c[oc] = w2s[oc * CHn + ty * 6 + j];
#pragma unroll
                for (int i = 0; i < 2; ++i) {
                    float lo, hi;
                    asm("mov.b64 {%0, %1}, %2;"
                        : "=f"(lo), "=f"(hi) : "l"(acc[g * 2 + i][jp]));
                    float r = fmaxf(half ? hi : lo, 0.f);
#pragma unroll
                    for (int oc = 0; oc < 12; ++oc)
                        pu[i][oc] = fmaf(r, w2c[oc], pu[i][oc]);
                }
            }
        }
        // butterfly reduce over the 16 ty lanes (lane bits 0..3)
#pragma unroll
        for (int i = 0; i < 2; ++i)
#pragma unroll
            for (int oc = 0; oc < 12; ++oc) {
                float v = pu[i][oc];
                v += __shfl_xor_sync(0xffffffffu, v, 1);
                v += __shfl_xor_sync(0xffffffffu, v, 2);
                v += __shfl_xor_sync(0xffffffffu, v, 4);
                v += __shfl_xor_sync(0xffffffffu, v, 8);
                if (ty == 0)
                    upd[(pbase + g * 2 + i) * 12 + oc] = v;
            }
    }

    __syncthreads();

    // ---- epilogue: out = x + (update + b2) * (mask > 0.5) -----------------
    for (int idx = tid; idx < PIX * Cn; idx += 256) {
        int oc = idx >> 7;       // / 128
        int px = idx & 127;
        float m  = (mask[gy * Wn + x0 + px] > 0.5f) ? 1.f : 0.f;
        float xc = xsd[2 * ((oc * 3 + 1) * PPAD + 1 + px)];   // lo of dup pair
        float u  = upd[px * 12 + oc] + __ldg(&b2[oc]);
        out[((b * Cn + oc) * Hn + gy) * Wn + x0 + px] = fmaf(u, m, xc);
    }
}

// ---------------------------------------------------------------------------
extern "C" void kernel_launch(void* const* d_in, const int* in_sizes, int n_in,
                              void* d_out, int out_size) {
    const float* x      = (const float*)d_in[0];
    const float* w_perc = (const float*)d_in[1];
    const float* w1     = (const float*)d_in[2];
    const float* b1     = (const float*)d_in[3];
    const float* w2     = (const float*)d_in[4];
    const float* b2     = (const float*)d_in[5];
    const float* mask   = (const float*)d_in[6];
    float* out          = (float*)d_out;

    const int smem_bytes = (Cn * 3 * PPAD * 2 + Kn * CHn + Cn * CHn + CHn +
                            PIX * Cn) * (int)sizeof(float);   // 90048 B
    cudaFuncSetAttribute(nca_kernel,
                         cudaFuncAttributeMaxDynamicSharedMemorySize,
                         smem_bytes);

    fold_kernel<<<Kn, CHn>>>(w1, w_perc);
    dim3 grid(Wn / PIX, Hn, Bn);
    nca_kernel<<<grid, 256, smem_bytes>>>(x, b1, w2, b2, mask, out);
}